// round 1
// baseline (speedup 1.0000x reference)
#include <cuda_runtime.h>
#include <math.h>

// Problem constants (fixed by the reference)
#define CW_ROW   128      // K*D = 2*64 floats per class
#define DHALF    32       // DH
#define NPTS     2048     // P
#define NBATCH   512      // B
#define MC_MULT  (4.0f / 2048.0f)
#define EPS_F    1e-9f

#define TPB       256
#define TILE_PTS  256                 // points per smem tile
#define PT_STRIDE 36                  // padded stride (floats) -> conflict-free LDS
#define NTILES    (NPTS / TILE_PTS)   // 8
#define GROUPS    (TPB / 4)           // 64 point-groups per iteration
#define ITERS     (TILE_PTS / GROUPS) // 4 iterations per tile

// Per-block partial sums (deterministic two-pass reduction; no atomics).
__device__ float g_partials[NBATCH];

__global__ __launch_bounds__(TPB)
void multibox_main_kernel(const float* __restrict__ cw,
                          const float* __restrict__ pts,
                          const int*   __restrict__ nf1)
{
    __shared__ float s_pts[TILE_PTS * PT_STRIDE]; // 36 KB
    __shared__ float s_w[2 * CW_ROW];             // the two gathered class rows
    __shared__ float s_red[TPB];

    const int tid = threadIdx.x;
    const int b   = blockIdx.x;

    // Gather the two class rows into shared (coalesced-ish, one time).
    {
        const int ic = nf1[2 * b + 0];
        const int id = nf1[2 * b + 1];
        if (tid < 128)       s_w[tid] = cw[(long)ic * CW_ROW + tid];
        else if (tid < 256)  s_w[tid] = cw[(long)id * CW_ROW + (tid - 128)];
    }
    __syncthreads();

    // Thread's box: j in 0..3.  j<2 -> class c (k=j), j>=2 -> class d (k=j-2).
    const int j = tid & 3;
    const float* row = s_w + (j >> 1) * CW_ROW + (j & 1) * 64;

    float lo[DHALF], hi[DHALF];
#pragma unroll
    for (int d = 0; d < DHALF; d++) {
        float c = row[d];
        float o = fabsf(row[d + DHALF]);
        lo[d] = c - o;
        hi[d] = c + o;
    }

    float acc = 0.0f;
    const float4* __restrict__ pts4 = (const float4*)pts;
    const int pg = tid >> 2; // point-group within iteration, 0..63

    for (int tile = 0; tile < NTILES; tile++) {
        __syncthreads(); // previous tile's compute done before overwrite
        // Stage 256 points (256*32 floats) into padded smem, coalesced LDG.128
#pragma unroll
        for (int i = 0; i < (TILE_PTS * 8) / TPB; i++) {   // 8 float4 per thread
            int f  = tid + i * TPB;                        // float4 index in tile
            int pi = f >> 3, q = f & 7;
            float4 v = pts4[tile * TILE_PTS * 8 + f];
            *(float4*)&s_pts[pi * PT_STRIDE + q * 4] = v;
        }
        __syncthreads();

#pragma unroll
        for (int it = 0; it < ITERS; it++) {
            const int pi = it * GROUPS + pg;
            const float* pp = &s_pts[pi * PT_STRIDE];

            // 4 independent min-chains for ILP
            float m0 = 1e30f, m1 = 1e30f, m2 = 1e30f, m3 = 1e30f;
#pragma unroll
            for (int q = 0; q < 8; q++) {
                float4 v = *(const float4*)(pp + q * 4);
                m0 = fminf(m0, fminf(v.x - lo[4*q+0], hi[4*q+0] - v.x));
                m1 = fminf(m1, fminf(v.y - lo[4*q+1], hi[4*q+1] - v.y));
                m2 = fminf(m2, fminf(v.z - lo[4*q+2], hi[4*q+2] - v.z));
                m3 = fminf(m3, fminf(v.w - lo[4*q+3], hi[4*q+3] - v.w));
            }
            float m = fminf(fminf(m0, m1), fminf(m2, m3));

            // Combine across the 4-lane group: max over K boxes per class,
            // then exchange class margins.
            const unsigned mask = 0xFFFFFFFFu;
            float mm    = fmaxf(m, __shfl_xor_sync(mask, m, 1)); // per-class max margin
            float other = __shfl_xor_sync(mask, mm, 2);          // the other class's margin

            if (j == 0) {
                // mm = class-c margin, other = class-d margin
                float ci = 1.0f / (1.0f + __expf(-mm));
                float di = 1.0f / (1.0f + __expf(-other));
                float a1 = fmaxf(ci - 0.5f, 0.0f) * MC_MULT;
                float ia = fmaxf(0.5f * (ci + di) - 0.5f, 0.0f) * MC_MULT;
                acc += 1.0f - ia / (a1 + EPS_F);
            }
        }
    }

    // Deterministic fixed-tree block reduction.
    s_red[tid] = acc;
    __syncthreads();
#pragma unroll
    for (int s = TPB / 2; s > 0; s >>= 1) {
        if (tid < s) s_red[tid] += s_red[tid + s];
        __syncthreads();
    }
    if (tid == 0) g_partials[b] = s_red[0];
}

__global__ __launch_bounds__(NBATCH)
void multibox_finalize_kernel(float* __restrict__ out)
{
    __shared__ double sd[NBATCH];
    const int t = threadIdx.x;
    sd[t] = (double)g_partials[t];
    __syncthreads();
#pragma unroll
    for (int s = NBATCH / 2; s > 0; s >>= 1) {
        if (t < s) sd[t] += sd[t + s];
        __syncthreads();
    }
    if (t == 0) {
        double loss = sd[0] / ((double)NBATCH * (double)NPTS);
        out[0] = fmaxf((float)loss, 0.0f);
    }
}

extern "C" void kernel_launch(void* const* d_in, const int* in_sizes, int n_in,
                              void* d_out, int out_size)
{
    const float* cw  = (const float*)d_in[0];  // class_weight [50000,128]
    const float* pts = (const float*)d_in[1];  // mc_points    [2048,32]
    const int*   nf1 = (const int*)  d_in[2];  // nf1_data     [512,2]
    float* out = (float*)d_out;

    multibox_main_kernel<<<NBATCH, TPB>>>(cw, pts, nf1);
    multibox_finalize_kernel<<<1, NBATCH>>>(out);
}

// round 2
// speedup vs baseline: 1.2803x; 1.2803x over previous
#include <cuda_runtime.h>
#include <math.h>

// Fixed problem shape
#define CW_ROW   128      // K*D floats per class
#define DHALF    32
#define NPTS     2048
#define NBATCH   512
#define MC_MULT  (4.0f / 2048.0f)
#define EPS_F    1e-9f

#define TPB       256
#define TILE_PTS  256
#define PT_STRIDE 36                 // padded floats per point -> conflict-free smem
#define BPB       2                  // batches per block (share point tiles)
#define TILESPB   2                  // tiles per block
#define NSPLIT    ((NPTS/TILE_PTS)/TILESPB)        // 4
#define GRID      ((NBATCH/BPB) * NSPLIT)          // 1024

__device__ float        g_partials[GRID];
__device__ unsigned int g_count;     // zero-init; last block resets -> replay-safe

__global__ __launch_bounds__(TPB, 2)
void multibox_kernel(const float* __restrict__ cw,
                     const float* __restrict__ pts,
                     const int*   __restrict__ nf1,
                     float*       __restrict__ out)
{
    __shared__ __align__(16) float s_pts[TILE_PTS * PT_STRIDE]; // 36 KB
    __shared__ float s_w[4 * CW_ROW];   // 2 batches x 2 classes
    __shared__ float s_red[TPB];
    __shared__ int   s_last;

    const int tid = threadIdx.x;
    const int bid = blockIdx.x;
    const int bp  = bid >> 2;   // batch pair 0..255
    const int ts  = bid & 3;    // tile split 0..3

    // Gather the 4 class rows (2 batches x {c,d}) into shared.
#pragma unroll
    for (int r = 0; r < 2; r++) {
        int idx = tid + r * TPB;          // 0..511
        int row = idx >> 7;               // 0..3
        int col = idx & 127;
        int bb  = bp * 2 + (row >> 1);
        int cl  = nf1[2 * bb + (row & 1)];
        s_w[idx] = cw[(long)cl * CW_ROW + col];
    }
    __syncthreads();

    // 8-lane groups: j = (batch-sel, box).  box: 0,1 -> class c k0,k1; 2,3 -> class d.
    const int j    = tid & 7;
    const int bsel = j >> 2;
    const int box  = j & 3;
    const float* w = s_w + (bsel * 2 + (box >> 1)) * CW_ROW + (box & 1) * 64;

    float c[DHALF], off[DHALF];
#pragma unroll
    for (int d = 0; d < DHALF; d++) {
        c[d]   = w[d];
        off[d] = fabsf(w[d + DHALF]);
    }

    float acc = 0.0f;
    const float4* __restrict__ pts4 = (const float4*)pts;
    const int  pg   = tid >> 3;          // point group 0..31
    const bool lead = (box == 0);

    for (int t = 0; t < TILESPB; t++) {
        const int tile = ts * TILESPB + t;
        __syncthreads();   // previous tile's compute done
#pragma unroll
        for (int i = 0; i < (TILE_PTS * 8) / TPB; i++) {   // 8 float4/thread
            int f  = tid + i * TPB;
            int pi = f >> 3, q = f & 7;
            float4 v = pts4[tile * TILE_PTS * 8 + f];
            *(float4*)&s_pts[pi * PT_STRIDE + q * 4] = v;
        }
        __syncthreads();

#pragma unroll 2
        for (int it = 0; it < TILE_PTS / 32; it++) {       // 8 iters
            const float* pp = &s_pts[(it * 32 + pg) * PT_STRIDE];

            // margin = min_d ( off[d] - |p[d] - c[d]| ), 4 chains for ILP.
            float m0 = 1e30f, m1 = 1e30f, m2 = 1e30f, m3 = 1e30f;
#pragma unroll
            for (int q = 0; q < 8; q++) {
                float4 v = *(const float4*)(pp + q * 4);
                m0 = fminf(m0, off[4*q+0] - fabsf(v.x - c[4*q+0]));
                m1 = fminf(m1, off[4*q+1] - fabsf(v.y - c[4*q+1]));
                m2 = fminf(m2, off[4*q+2] - fabsf(v.z - c[4*q+2]));
                m3 = fminf(m3, off[4*q+3] - fabsf(v.w - c[4*q+3]));
            }
            float m = fminf(fminf(m0, m1), fminf(m2, m3));

            const unsigned msk = 0xFFFFFFFFu;
            float mm    = fmaxf(m, __shfl_xor_sync(msk, m, 1)); // max over K
            float other = __shfl_xor_sync(msk, mm, 2);          // other class

            // Branchless epilogue (computed warp-wide, accumulated on box==0 lanes)
            float ci = __fdividef(1.0f, 1.0f + __expf(-mm));
            float di = __fdividef(1.0f, 1.0f + __expf(-other));
            float a1 = fmaxf(ci - 0.5f, 0.0f) * MC_MULT;
            float ia = fmaxf(0.5f * (ci + di) - 0.5f, 0.0f) * MC_MULT;
            float term = 1.0f - __fdividef(ia, a1 + EPS_F);
            acc += lead ? term : 0.0f;
        }
    }

    // Deterministic fixed-tree block reduction.
    s_red[tid] = acc;
    __syncthreads();
#pragma unroll
    for (int s = TPB / 2; s > 0; s >>= 1) {
        if (tid < s) s_red[tid] += s_red[tid + s];
        __syncthreads();
    }

    // Last-block final reduce (threadfence-reduction pattern; deterministic tree).
    if (tid == 0) {
        g_partials[bid] = s_red[0];
        __threadfence();
        unsigned old = atomicAdd(&g_count, 1u);
        s_last = (old == GRID - 1);
    }
    __syncthreads();

    if (s_last) {
        double* sd = (double*)s_pts;   // reuse tile smem (16B aligned)
        double v = 0.0;
#pragma unroll
        for (int i = 0; i < GRID / TPB; i++)
            v += (double)__ldcg(&g_partials[tid + i * TPB]);
        sd[tid] = v;
        __syncthreads();
#pragma unroll
        for (int s = TPB / 2; s > 0; s >>= 1) {
            if (tid < s) sd[tid] += sd[tid + s];
            __syncthreads();
        }
        if (tid == 0) {
            double loss = sd[0] / ((double)NBATCH * (double)NPTS);
            out[0] = loss > 0.0 ? (float)loss : 0.0f;
            g_count = 0;   // reset for next graph replay
        }
    }
}

extern "C" void kernel_launch(void* const* d_in, const int* in_sizes, int n_in,
                              void* d_out, int out_size)
{
    const float* cw  = (const float*)d_in[0];  // [50000,128]
    const float* pts = (const float*)d_in[1];  // [2048,32]
    const int*   nf1 = (const int*)  d_in[2];  // [512,2]
    multibox_kernel<<<GRID, TPB>>>(cw, pts, nf1, (float*)d_out);
}

// round 4
// speedup vs baseline: 1.9677x; 1.5369x over previous
#include <cuda_runtime.h>
#include <math.h>

// Fixed problem shape
#define CW_ROW   128
#define NPTS     2048
#define NBATCH   512
#define MC_MULT  (4.0f / 2048.0f)
#define EPS_F    1e-9f

#define TPB       256
#define TILE_PTS  128
#define PT_STRIDE 36                        // padded floats/point -> conflict-free smem
#define NSPLIT    (NPTS / TILE_PTS)         // 16
#define GRID      ((NBATCH / 8) * NSPLIT)   // 1024

__device__ float        g_partials[GRID];
__device__ unsigned int g_count;            // zero-init; last block resets -> replay-safe

// FFMA with immediate 1.0 multiplier: rt=1 on the fma pipe (vs FADD rt=2).
__device__ __forceinline__ float ffma1(float p, float nc) {
    float t;
    asm("fma.rn.f32 %0, %1, 0f3F800000, %2;" : "=f"(t) : "f"(p), "f"(nc));
    return t;
}

__global__ __launch_bounds__(TPB, 4)
void multibox_kernel(const float* __restrict__ cw,
                     const float* __restrict__ pts,
                     const int*   __restrict__ nf1,
                     float*       __restrict__ out)
{
    __shared__ __align__(16) float s_pts[TILE_PTS * PT_STRIDE]; // 18 KB
    __shared__ float s_stash[8 * 64];                           // 2 KB (per-warp 32 float2)
    __shared__ float s_red[TPB];
    __shared__ int   s_last;

    const int tid  = threadIdx.x;
    const int bid  = blockIdx.x;
    const int bg   = bid >> 4;      // batch group 0..63
    const int ts   = bid & 15;      // point-tile split 0..15

    const int w    = tid >> 5;      // warp -> batch within group
    const int lane = tid & 31;
    const int g    = lane >> 3;     // point within iteration, 0..3
    const int j    = lane & 7;
    const int box  = j >> 1;        // 0,1: class c ; 2,3: class d
    const int half = j & 1;         // which 16 of the 32 dims

    // ---- this lane's 16-dim box slice: nc = -center, off = |offset| ----
    const int batch = bg * 8 + w;
    const int cls   = nf1[2 * batch + (box >> 1)];
    const float* p0 = cw + (long)cls * CW_ROW + (box & 1) * 64 + half * 16;

    float nc[16], off[16];
#pragma unroll
    for (int q = 0; q < 4; q++) {
        float4 cv = *(const float4*)(p0 + q * 4);
        float4 ov = *(const float4*)(p0 + 32 + q * 4);
        nc[4*q+0] = -cv.x; nc[4*q+1] = -cv.y; nc[4*q+2] = -cv.z; nc[4*q+3] = -cv.w;
        off[4*q+0] = fabsf(ov.x); off[4*q+1] = fabsf(ov.y);
        off[4*q+2] = fabsf(ov.z); off[4*q+3] = fabsf(ov.w);
    }

    // ---- stage the 128-point tile (coalesced LDG.128 -> padded smem) ----
    const float4* __restrict__ pts4 = (const float4*)pts;
#pragma unroll
    for (int i = 0; i < (TILE_PTS * 8) / TPB; i++) {   // 4 float4 / thread
        int f  = tid + i * TPB;
        int pi = f >> 3, q = f & 7;
        float4 v = pts4[ts * TILE_PTS * 8 + f];
        *(float4*)&s_pts[pi * PT_STRIDE + q * 4] = v;
    }
    __syncthreads();

    float acc = 0.0f;
    const int wst = w * 64;

#pragma unroll 8
    for (int it = 0; it < TILE_PTS / 4; it++) {        // 32 iters, 4 points/warp
        const float* pp = &s_pts[(it * 4 + g) * PT_STRIDE + half * 16];
        float4 v0 = *(const float4*)(pp +  0);
        float4 v1 = *(const float4*)(pp +  4);
        float4 v2 = *(const float4*)(pp +  8);
        float4 v3 = *(const float4*)(pp + 12);

        // margin chain: off[d] - |p[d] - c[d]| ; 4 independent chains
        float m0 = off[ 0] - fabsf(ffma1(v0.x, nc[ 0]));
        float m1 = off[ 1] - fabsf(ffma1(v0.y, nc[ 1]));
        float m2 = off[ 2] - fabsf(ffma1(v0.z, nc[ 2]));
        float m3 = off[ 3] - fabsf(ffma1(v0.w, nc[ 3]));
        m0 = fminf(m0, off[ 4] - fabsf(ffma1(v1.x, nc[ 4])));
        m1 = fminf(m1, off[ 5] - fabsf(ffma1(v1.y, nc[ 5])));
        m2 = fminf(m2, off[ 6] - fabsf(ffma1(v1.z, nc[ 6])));
        m3 = fminf(m3, off[ 7] - fabsf(ffma1(v1.w, nc[ 7])));
        m0 = fminf(m0, off[ 8] - fabsf(ffma1(v2.x, nc[ 8])));
        m1 = fminf(m1, off[ 9] - fabsf(ffma1(v2.y, nc[ 9])));
        m2 = fminf(m2, off[10] - fabsf(ffma1(v2.z, nc[10])));
        m3 = fminf(m3, off[11] - fabsf(ffma1(v2.w, nc[11])));
        m0 = fminf(m0, off[12] - fabsf(ffma1(v3.x, nc[12])));
        m1 = fminf(m1, off[13] - fabsf(ffma1(v3.y, nc[13])));
        m2 = fminf(m2, off[14] - fabsf(ffma1(v3.z, nc[14])));
        m3 = fminf(m3, off[15] - fabsf(ffma1(v3.w, nc[15])));
        float m = fminf(fminf(m0, m1), fminf(m2, m3));

        const unsigned msk = 0xFFFFFFFFu;
        m = fminf(m, __shfl_xor_sync(msk, m, 1));            // min over halves
        float mm    = fmaxf(m, __shfl_xor_sync(msk, m, 2));  // max over K -> class margin
        float other = __shfl_xor_sync(msk, mm, 4);           // other class's margin

        if (j == 0)
            *(float2*)&s_stash[wst + ((it & 7) * 4 + g) * 2] = make_float2(mm, other);

        if ((it & 7) == 7) {       // full-warp epilogue over 32 stashed pairs
            __syncwarp();
            float2 pr = *(const float2*)&s_stash[wst + lane * 2];
            float ci  = __fdividef(1.0f, 1.0f + __expf(-pr.x));
            float di  = __fdividef(1.0f, 1.0f + __expf(-pr.y));
            float a1e = fmaxf(ci - 0.5f, 0.0f) * MC_MULT;
            float ia  = fmaxf(0.5f * (ci + di) - 0.5f, 0.0f) * MC_MULT;
            acc += 1.0f - __fdividef(ia, a1e + EPS_F);
            __syncwarp();
        }
    }

    // ---- deterministic fixed-tree block reduction ----
    s_red[tid] = acc;
    __syncthreads();
#pragma unroll
    for (int s = TPB / 2; s > 0; s >>= 1) {
        if (tid < s) s_red[tid] += s_red[tid + s];
        __syncthreads();
    }

    if (tid == 0) {
        g_partials[bid] = s_red[0];
        __threadfence();
        unsigned old = atomicAdd(&g_count, 1u);
        s_last = (old == GRID - 1);
    }
    __syncthreads();

    if (s_last) {
        double* sd = (double*)s_pts;   // reuse tile smem
        double v = 0.0;
#pragma unroll
        for (int i = 0; i < GRID / TPB; i++)
            v += (double)__ldcg(&g_partials[tid + i * TPB]);
        sd[tid] = v;
        __syncthreads();
#pragma unroll
        for (int s = TPB / 2; s > 0; s >>= 1) {
            if (tid < s) sd[tid] += sd[tid + s];
            __syncthreads();
        }
        if (tid == 0) {
            double loss = sd[0] / ((double)NBATCH * (double)NPTS);
            out[0] = loss > 0.0 ? (float)loss : 0.0f;
            g_count = 0;
        }
    }
}

extern "C" void kernel_launch(void* const* d_in, const int* in_sizes, int n_in,
                              void* d_out, int out_size)
{
    const float* cw  = (const float*)d_in[0];  // [50000,128]
    const float* pts = (const float*)d_in[1];  // [2048,32]
    const int*   nf1 = (const int*)  d_in[2];  // [512,2]
    multibox_kernel<<<GRID, TPB>>>(cw, pts, nf1, (float*)d_out);
}

// round 5
// speedup vs baseline: 2.1058x; 1.0702x over previous
#include <cuda_runtime.h>
#include <math.h>

// Fixed problem shape
#define CW_ROW   128
#define NPTS     2048
#define NBATCH   512
#define MC_MULT  (4.0f / 2048.0f)
#define EPS_F    1e-9f

#define TPB       256
#define TILE_PTS  128
#define PT_STRIDE 36                        // padded floats/point -> conflict-free smem
#define NSPLIT    (NPTS / TILE_PTS)         // 16
#define GRID      ((NBATCH / 8) * NSPLIT)   // 1024
#define STASH_W   288                       // 32 points * stride 9 per warp

__device__ float        g_partials[GRID];
__device__ unsigned int g_count;            // zero-init; last block resets -> replay-safe

// FFMA with immediate 1.0 multiplier: rt=1 on the fma pipe (vs FADD rt=2).
__device__ __forceinline__ float ffma1(float p, float nc) {
    float t;
    asm("fma.rn.f32 %0, %1, 0f3F800000, %2;" : "=f"(t) : "f"(p), "f"(nc));
    return t;
}

__global__ __launch_bounds__(TPB, 4)
void multibox_kernel(const float* __restrict__ cw,
                     const float* __restrict__ pts,
                     const int*   __restrict__ nf1,
                     float*       __restrict__ out)
{
    __shared__ __align__(16) float s_pts[TILE_PTS * PT_STRIDE]; // 18 KB
    __shared__ float s_stash[8 * STASH_W];                      // 9 KB margin stash
    __shared__ float s_red[TPB];
    __shared__ int   s_last;

    const int tid  = threadIdx.x;
    const int bid  = blockIdx.x;
    const int bg   = bid >> 4;      // batch group 0..63
    const int ts   = bid & 15;      // point-tile split 0..15

    const int w    = tid >> 5;      // warp -> batch within group
    const int lane = tid & 31;
    const int g    = lane >> 3;     // point within iteration, 0..3
    const int j    = lane & 7;
    const int box  = j >> 1;        // 0,1: class c ; 2,3: class d
    const int half = j & 1;         // which 16 of the 32 dims

    // ---- this lane's 16-dim box slice: nc = -center, off = |offset| ----
    const int batch = bg * 8 + w;
    const int cls   = nf1[2 * batch + (box >> 1)];
    const float* p0 = cw + (long)cls * CW_ROW + (box & 1) * 64 + half * 16;

    float nc[16], off[16];
#pragma unroll
    for (int q = 0; q < 4; q++) {
        float4 cv = *(const float4*)(p0 + q * 4);
        float4 ov = *(const float4*)(p0 + 32 + q * 4);
        nc[4*q+0] = -cv.x; nc[4*q+1] = -cv.y; nc[4*q+2] = -cv.z; nc[4*q+3] = -cv.w;
        off[4*q+0] = fabsf(ov.x); off[4*q+1] = fabsf(ov.y);
        off[4*q+2] = fabsf(ov.z); off[4*q+3] = fabsf(ov.w);
    }

    // ---- stage the 128-point tile (coalesced LDG.128 -> padded smem) ----
    const float4* __restrict__ pts4 = (const float4*)pts;
#pragma unroll
    for (int i = 0; i < (TILE_PTS * 8) / TPB; i++) {   // 4 float4 / thread
        int f  = tid + i * TPB;
        int pi = f >> 3, q = f & 7;
        float4 v = pts4[ts * TILE_PTS * 8 + f];
        *(float4*)&s_pts[pi * PT_STRIDE + q * 4] = v;
    }
    __syncthreads();

    float acc = 0.0f;
    float* wst = &s_stash[w * STASH_W];

#pragma unroll 8
    for (int it = 0; it < TILE_PTS / 4; it++) {        // 32 iters, 4 points/warp
        const float* pp = &s_pts[(it * 4 + g) * PT_STRIDE + half * 16];
        float4 v0 = *(const float4*)(pp +  0);
        float4 v1 = *(const float4*)(pp +  4);
        float4 v2 = *(const float4*)(pp +  8);
        float4 v3 = *(const float4*)(pp + 12);

        // margin chains: off[d] - |p[d] - c[d]| ; 4 independent chains for ILP
        float m0 = off[ 0] - fabsf(ffma1(v0.x, nc[ 0]));
        float m1 = off[ 1] - fabsf(ffma1(v0.y, nc[ 1]));
        float m2 = off[ 2] - fabsf(ffma1(v0.z, nc[ 2]));
        float m3 = off[ 3] - fabsf(ffma1(v0.w, nc[ 3]));
        m0 = fminf(m0, off[ 4] - fabsf(ffma1(v1.x, nc[ 4])));
        m1 = fminf(m1, off[ 5] - fabsf(ffma1(v1.y, nc[ 5])));
        m2 = fminf(m2, off[ 6] - fabsf(ffma1(v1.z, nc[ 6])));
        m3 = fminf(m3, off[ 7] - fabsf(ffma1(v1.w, nc[ 7])));
        m0 = fminf(m0, off[ 8] - fabsf(ffma1(v2.x, nc[ 8])));
        m1 = fminf(m1, off[ 9] - fabsf(ffma1(v2.y, nc[ 9])));
        m2 = fminf(m2, off[10] - fabsf(ffma1(v2.z, nc[10])));
        m3 = fminf(m3, off[11] - fabsf(ffma1(v2.w, nc[11])));
        m0 = fminf(m0, off[12] - fabsf(ffma1(v3.x, nc[12])));
        m1 = fminf(m1, off[13] - fabsf(ffma1(v3.y, nc[13])));
        m2 = fminf(m2, off[14] - fabsf(ffma1(v3.z, nc[14])));
        m3 = fminf(m3, off[15] - fabsf(ffma1(v3.w, nc[15])));
        float m = fminf(fminf(m0, m1), fminf(m2, m3));

        // one STS.32 per lane: stash[(point within 8-iter batch) * 9 + j]
        wst[((it & 7) * 4 + g) * 9 + j] = m;

        if ((it & 7) == 7) {
            // bulk combine: lane p handles point p (no shuffles, full ILP)
            __syncwarp();
            const float* sp = &wst[lane * 9];
            float s0 = sp[0], s1 = sp[1], s2 = sp[2], s3 = sp[3];
            float s4 = sp[4], s5 = sp[5], s6 = sp[6], s7 = sp[7];
            float mc = fmaxf(fminf(s0, s1), fminf(s2, s3));   // class c margin
            float md = fmaxf(fminf(s4, s5), fminf(s6, s7));   // class d margin

            float ci  = __fdividef(1.0f, 1.0f + __expf(-mc));
            float di  = __fdividef(1.0f, 1.0f + __expf(-md));
            float a1e = fmaxf(ci - 0.5f, 0.0f) * MC_MULT;
            float ia  = fmaxf(0.5f * (ci + di) - 0.5f, 0.0f) * MC_MULT;
            acc += 1.0f - __fdividef(ia, a1e + EPS_F);
            __syncwarp();   // stash consumed before next batch overwrites
        }
    }

    // ---- deterministic fixed-tree block reduction ----
    s_red[tid] = acc;
    __syncthreads();
#pragma unroll
    for (int s = TPB / 2; s > 0; s >>= 1) {
        if (tid < s) s_red[tid] += s_red[tid + s];
        __syncthreads();
    }

    if (tid == 0) {
        g_partials[bid] = s_red[0];
        __threadfence();
        unsigned old = atomicAdd(&g_count, 1u);
        s_last = (old == GRID - 1);
    }
    __syncthreads();

    if (s_last) {
        double* sd = (double*)s_pts;   // reuse tile smem
        double v = 0.0;
#pragma unroll
        for (int i = 0; i < GRID / TPB; i++)
            v += (double)__ldcg(&g_partials[tid + i * TPB]);
        sd[tid] = v;
        __syncthreads();
#pragma unroll
        for (int s = TPB / 2; s > 0; s >>= 1) {
            if (tid < s) sd[tid] += sd[tid + s];
            __syncthreads();
        }
        if (tid == 0) {
            double loss = sd[0] / ((double)NBATCH * (double)NPTS);
            out[0] = loss > 0.0 ? (float)loss : 0.0f;
            g_count = 0;
        }
    }
}

extern "C" void kernel_launch(void* const* d_in, const int* in_sizes, int n_in,
                              void* d_out, int out_size)
{
    const float* cw  = (const float*)d_in[0];  // [50000,128]
    const float* pts = (const float*)d_in[1];  // [2048,32]
    const int*   nf1 = (const int*)  d_in[2];  // [512,2]
    multibox_kernel<<<GRID, TPB>>>(cw, pts, nf1, (float*)d_out);
}

// round 6
// speedup vs baseline: 2.1081x; 1.0011x over previous
#include <cuda_runtime.h>
#include <math.h>

// Fixed problem shape
#define CW_ROW   128
#define NPTS     2048
#define NBATCH   512
#define MC_MULT  (4.0f / 2048.0f)
#define EPS_F    1e-9f

#define TPB       256
#define TILE_PTS  128                       // points per block (per warp)
#define NSPLIT    (NPTS / TILE_PTS)         // 16
#define GRID      ((NBATCH / 8) * NSPLIT)   // 1024
#define SSTR      20                        // stash stride (floats/point), 16B-aligned

__device__ float        g_partials[GRID];
__device__ unsigned int g_count;            // zero-init; last block resets -> replay-safe

// FFMA with immediate 1.0 multiplier: rt=1 on the fma pipe (vs FADD rt=2).
__device__ __forceinline__ float ffma1(float p, float nc) {
    float t;
    asm("fma.rn.f32 %0, %1, 0f3F800000, %2;" : "=f"(t) : "f"(p), "f"(nc));
    return t;
}

__global__ __launch_bounds__(TPB, 4)
void multibox_kernel(const float* __restrict__ cw,
                     const float* __restrict__ pts,
                     const int*   __restrict__ nf1,
                     float*       __restrict__ out)
{
    __shared__ __align__(16) float s_stash[8 * 32 * SSTR];  // 20 KB
    __shared__ float s_red[TPB];
    __shared__ int   s_last;

    const int tid  = threadIdx.x;
    const int bid  = blockIdx.x;
    const int bg   = bid >> 4;      // batch group 0..63
    const int ts   = bid & 15;      // point-tile split 0..15

    const int w    = tid >> 5;      // warp -> batch within group
    const int lane = tid & 31;
    const int g    = lane >> 3;     // point within iteration, 0..3
    const int j    = lane & 7;
    const int cl   = j >> 2;        // class: 0 -> c, 1 -> d
    const int qr   = j & 3;         // quarter: dims qr*8 .. qr*8+7

    // ---- this lane's params: both k-boxes of its class, its 8 dims ----
    const int batch = bg * 8 + w;
    const int cls   = nf1[2 * batch + cl];
    const float* row = cw + (long)cls * CW_ROW + qr * 8;   // k0 center base

    float nc0[8], of0[8], nc1[8], of1[8];
#pragma unroll
    for (int q = 0; q < 2; q++) {
        float4 c0 = *(const float4*)(row +       q * 4);   // k0 center
        float4 o0 = *(const float4*)(row +  32 + q * 4);   // k0 offset
        float4 c1 = *(const float4*)(row +  64 + q * 4);   // k1 center
        float4 o1 = *(const float4*)(row +  96 + q * 4);   // k1 offset
        nc0[4*q+0] = -c0.x; nc0[4*q+1] = -c0.y; nc0[4*q+2] = -c0.z; nc0[4*q+3] = -c0.w;
        of0[4*q+0] = fabsf(o0.x); of0[4*q+1] = fabsf(o0.y);
        of0[4*q+2] = fabsf(o0.z); of0[4*q+3] = fabsf(o0.w);
        nc1[4*q+0] = -c1.x; nc1[4*q+1] = -c1.y; nc1[4*q+2] = -c1.z; nc1[4*q+3] = -c1.w;
        of1[4*q+0] = fabsf(o1.x); of1[4*q+1] = fabsf(o1.y);
        of1[4*q+2] = fabsf(o1.z); of1[4*q+3] = fabsf(o1.w);
    }

    const float* pbase = pts + (long)(ts * TILE_PTS) * 32 + qr * 8;
    float* wst = &s_stash[w * 32 * SSTR];
    float acc = 0.0f;

#pragma unroll 8
    for (int it = 0; it < TILE_PTS / 4; it++) {            // 32 iters, 4 points/warp
        const float* pp = pbase + (it * 4 + g) * 32;
        float4 v0 = *(const float4*)(pp);                  // dims qr*8+0..3
        float4 v1 = *(const float4*)(pp + 4);              // dims qr*8+4..7

        // k0 margin over this lane's 8 dims (2 chains)
        float a0 = of0[0] - fabsf(ffma1(v0.x, nc0[0]));
        float a1 = of0[1] - fabsf(ffma1(v0.y, nc0[1]));
        a0 = fminf(a0, of0[2] - fabsf(ffma1(v0.z, nc0[2])));
        a1 = fminf(a1, of0[3] - fabsf(ffma1(v0.w, nc0[3])));
        a0 = fminf(a0, of0[4] - fabsf(ffma1(v1.x, nc0[4])));
        a1 = fminf(a1, of0[5] - fabsf(ffma1(v1.y, nc0[5])));
        a0 = fminf(a0, of0[6] - fabsf(ffma1(v1.z, nc0[6])));
        a1 = fminf(a1, of0[7] - fabsf(ffma1(v1.w, nc0[7])));
        float mk0 = fminf(a0, a1);

        // k1 margin over the same 8 dims
        float b0 = of1[0] - fabsf(ffma1(v0.x, nc1[0]));
        float b1 = of1[1] - fabsf(ffma1(v0.y, nc1[1]));
        b0 = fminf(b0, of1[2] - fabsf(ffma1(v0.z, nc1[2])));
        b1 = fminf(b1, of1[3] - fabsf(ffma1(v0.w, nc1[3])));
        b0 = fminf(b0, of1[4] - fabsf(ffma1(v1.x, nc1[4])));
        b1 = fminf(b1, of1[5] - fabsf(ffma1(v1.y, nc1[5])));
        b0 = fminf(b0, of1[6] - fabsf(ffma1(v1.z, nc1[6])));
        b1 = fminf(b1, of1[7] - fabsf(ffma1(v1.w, nc1[7])));
        float mk1 = fminf(b0, b1);

        // one STS.64: stash[(point slot)*20 + j*2] = (mk0, mk1)
        *(float2*)&wst[((it & 7) * 4 + g) * SSTR + j * 2] = make_float2(mk0, mk1);

        if ((it & 7) == 7) {
            // bulk combine: lane p handles stashed point p (no shuffles)
            __syncwarp();
            const float* sp = &wst[lane * SSTR];
            float4 f0 = *(const float4*)(sp);       // class c: q0(k0,k1), q1(k0,k1)
            float4 f1 = *(const float4*)(sp +  4);  // class c: q2, q3
            float mc = fmaxf(fminf(fminf(f0.x, f0.z), fminf(f1.x, f1.z)),
                             fminf(fminf(f0.y, f0.w), fminf(f1.y, f1.w)));
            float4 f2 = *(const float4*)(sp +  8);  // class d: q0, q1
            float4 f3 = *(const float4*)(sp + 12);  // class d: q2, q3
            float md = fmaxf(fminf(fminf(f2.x, f2.z), fminf(f3.x, f3.z)),
                             fminf(fminf(f2.y, f2.w), fminf(f3.y, f3.w)));

            float ci  = __fdividef(1.0f, 1.0f + __expf(-mc));
            float di  = __fdividef(1.0f, 1.0f + __expf(-md));
            float a1e = fmaxf(ci - 0.5f, 0.0f) * MC_MULT;
            float ia  = fmaxf(0.5f * (ci + di) - 0.5f, 0.0f) * MC_MULT;
            acc += 1.0f - __fdividef(ia, a1e + EPS_F);
            __syncwarp();   // stash fully consumed before next batch overwrites
        }
    }

    // ---- deterministic fixed-tree block reduction ----
    s_red[tid] = acc;
    __syncthreads();
#pragma unroll
    for (int s = TPB / 2; s > 0; s >>= 1) {
        if (tid < s) s_red[tid] += s_red[tid + s];
        __syncthreads();
    }

    if (tid == 0) {
        g_partials[bid] = s_red[0];
        __threadfence();
        unsigned old = atomicAdd(&g_count, 1u);
        s_last = (old == GRID - 1);
    }
    __syncthreads();

    if (s_last) {
        double* sd = (double*)s_stash;   // reuse stash smem (16B aligned)
        double v = 0.0;
#pragma unroll
        for (int i = 0; i < GRID / TPB; i++)
            v += (double)__ldcg(&g_partials[tid + i * TPB]);
        sd[tid] = v;
        __syncthreads();
#pragma unroll
        for (int s = TPB / 2; s > 0; s >>= 1) {
            if (tid < s) sd[tid] += sd[tid + s];
            __syncthreads();
        }
        if (tid == 0) {
            double loss = sd[0] / ((double)NBATCH * (double)NPTS);
            out[0] = loss > 0.0 ? (float)loss : 0.0f;
            g_count = 0;
        }
    }
}

extern "C" void kernel_launch(void* const* d_in, const int* in_sizes, int n_in,
                              void* d_out, int out_size)
{
    const float* cw  = (const float*)d_in[0];  // [50000,128]
    const float* pts = (const float*)d_in[1];  // [2048,32]
    const int*   nf1 = (const int*)  d_in[2];  // [512,2]
    multibox_kernel<<<GRID, TPB>>>(cw, pts, nf1, (float*)d_out);
}